// round 1
// baseline (speedup 1.0000x reference)
#include <cuda_runtime.h>
#include <cstdint>

// ---------------------------------------------------------------------------
// 2-layer LSTM, B=64, S=512, I=64, H=512, fc head on final h1.
// Persistent kernel, 128 CTAs (64 per layer), grid barrier per phase.
// Phase p: layer0 computes step t=p (p<512), layer1 computes step t=p-1 (p>=1).
// Weights live in SMEM (tf32-rounded). GEMM via mma.sync m16n8k8 tf32.
// Activations stored transposed hT[n][b], pre-rounded to tf32.
// ---------------------------------------------------------------------------

#define NC    128       // persistent CTAs (<= 148 SMs -> all co-resident)
#define NTHR  128
#define BSZ   64
#define HID   512
#define INP   64
#define SEQ   512
#define K0    576       // I + H
#define K1    1024      // H + H
#define NK8_0 (K0/8)    // 72
#define NK8_1 (K1/8)    // 128
#define SMEM_W_FLOATS (1024*32)
#define SMEM_BYTES    (SMEM_W_FLOATS*4 + 128)

// persistent state / scratch (device globals: no allocation allowed)
__device__ float g_xT[SEQ*INP*BSZ];      // [t][i][b], tf32-rounded
__device__ float g_h0T[2][HID*BSZ];      // ping-pong [n][b]
__device__ float g_h1T[2][HID*BSZ];
__device__ float g_c0T[HID*BSZ];
__device__ float g_c1T[HID*BSZ];
__device__ unsigned g_arrive;
__device__ unsigned g_release;
__device__ unsigned g_exit;

__device__ __forceinline__ unsigned f2tf32(float f) {
    unsigned r;
    asm("cvt.rna.tf32.f32 %0, %1;" : "=r"(r) : "f"(f));
    return r;
}

__device__ __forceinline__ void mma8(float (&d)[4],
                                     unsigned a0, unsigned a1, unsigned a2, unsigned a3,
                                     unsigned b0, unsigned b1) {
    asm volatile(
        "mma.sync.aligned.m16n8k8.row.col.f32.tf32.tf32.f32 "
        "{%0,%1,%2,%3}, {%4,%5,%6,%7}, {%8,%9}, {%0,%1,%2,%3};"
        : "+f"(d[0]), "+f"(d[1]), "+f"(d[2]), "+f"(d[3])
        : "r"(a0), "r"(a1), "r"(a2), "r"(a3), "r"(b0), "r"(b1));
}

__device__ __forceinline__ float sigm(float x) { return 1.f / (1.f + __expf(-x)); }

// Grid barrier: generation-counted, sense via monotonically increasing release.
// All NC CTAs are guaranteed co-resident (grid <= #SMs, 1 CTA/SM via smem).
__device__ __forceinline__ void grid_bar(unsigned gen) {
    __syncthreads();
    if (threadIdx.x == 0) {
        __threadfence();
        const unsigned target = gen + 1u;
        unsigned prev = atomicAdd(&g_arrive, 1u);
        if (prev == target * NC - 1u) {
            atomicExch(&g_release, target);
        } else {
            while (*(volatile unsigned*)&g_release < target) __nanosleep(64);
        }
        __threadfence();
    }
    __syncthreads();
}

// K-loop: A fragments straight from global (L2), B fragments from SMEM weights.
// aoff = tig*BSZ + rowa ; boff = tig*32 + g*4
template <int NK8, int SPLIT>
__device__ __forceinline__ void gemm_tiles(float (&acc)[4][4],
                                           const float* __restrict__ aA,
                                           const float* __restrict__ aB,
                                           const float* __restrict__ sW,
                                           int aoff, int boff) {
#pragma unroll 4
    for (int k8 = 0; k8 < NK8; ++k8) {
        const float* ab = (k8 < SPLIT) ? (aA + k8 * (8 * BSZ))
                                       : (aB + (k8 - SPLIT) * (8 * BSZ));
        unsigned a0 = __float_as_uint(__ldcg(ab + aoff));
        unsigned a1 = __float_as_uint(__ldcg(ab + aoff + 8));
        unsigned a2 = __float_as_uint(__ldcg(ab + aoff + 4 * BSZ));
        unsigned a3 = __float_as_uint(__ldcg(ab + aoff + 4 * BSZ + 8));
        const float* bp = sW + k8 * 256 + boff;      // (k8*8+tig)*32 + g*4
        float4 bl = *(const float4*)bp;              // b0 for ntiles 0..3
        float4 bh = *(const float4*)(bp + 128);      // b1 (k+4)
        mma8(acc[0], a0, a1, a2, a3, __float_as_uint(bl.x), __float_as_uint(bh.x));
        mma8(acc[1], a0, a1, a2, a3, __float_as_uint(bl.y), __float_as_uint(bh.y));
        mma8(acc[2], a0, a1, a2, a3, __float_as_uint(bl.z), __float_as_uint(bh.z));
        mma8(acc[3], a0, a1, a2, a3, __float_as_uint(bl.w), __float_as_uint(bh.w));
    }
}

__global__ void __launch_bounds__(NTHR, 1)
lstm_persist(const float* __restrict__ W0, const float* __restrict__ b0,
             const float* __restrict__ W1, const float* __restrict__ b1,
             const float* __restrict__ Wfc, const float* __restrict__ bfc,
             float* __restrict__ out) {
    extern __shared__ float smem[];
    float* sW    = smem;
    float* sBias = smem + SMEM_W_FLOATS;

    const int cta  = blockIdx.x;
    const int tid  = threadIdx.x;
    const bool l0  = (cta < 64);
    const int lc   = l0 ? cta : cta - 64;
    const int n0   = lc * 8;                 // h-column base for this CTA
    const int lane = tid & 31, wrp = tid >> 5;
    const int g    = lane >> 2, tig = lane & 3;
    const int rowa = wrp * 16 + g;           // batch row (M) for a0
    const int aoff = tig * BSZ + rowa;
    const int boff = tig * 32 + g * 4;

    // ---- prologue: zero recurrent state (must re-zero every launch) ----
    {
        float* bufs[6] = { g_h0T[0], g_h0T[1], g_h1T[0], g_h1T[1], g_c0T, g_c1T };
#pragma unroll
        for (int z = 0; z < 6; ++z) {
            float* pz = bufs[z];
            for (int e = cta * NTHR + tid; e < HID * BSZ; e += NC * NTHR) pz[e] = 0.f;
        }
    }

    // ---- prologue: load weight slice into SMEM, interleaved for lds.128 ----
    // sW[k][j*4+q] = tf32(W[k][q*512 + n0 + j])   (q = gate i/f/g/o, j = 0..7)
    {
        const float* W    = l0 ? W0 : W1;
        const float* bias = l0 ? b0 : b1;
        const int K = l0 ? K0 : K1;
        for (int e = tid; e < K * 32; e += NTHR) {
            int k = e >> 5, m = e & 31;
            int q = m >> 3, j = m & 7;
            float w = W[k * 2048 + q * 512 + n0 + j];
            sW[k * 32 + j * 4 + q] = __uint_as_float(f2tf32(w));
        }
        if (tid < 32) {
            int q = tid >> 3, j = tid & 7;
            sBias[tid] = bias[q * 512 + n0 + j];   // sBias[q*8+j]
        }
    }

    grid_bar(0);
    unsigned gen = 1;

    // ---- main pipelined loop: 513 phases ----
    for (int p = 0; p <= SEQ; ++p, ++gen) {
        const int rb = (p + 1) & 1, wb = p & 1;
        const bool active = l0 ? (p < SEQ) : (p >= 1);
        if (active) {
            float acc[4][4];
#pragma unroll
            for (int q = 0; q < 4; ++q) {
                float be = sBias[q * 8 + 2 * tig];
                float bo = sBias[q * 8 + 2 * tig + 1];
                acc[q][0] = be; acc[q][1] = bo; acc[q][2] = be; acc[q][3] = bo;
            }

            if (l0) {
                // A = [x_t | h0(p-1)]
                gemm_tiles<NK8_0, INP / 8>(acc, g_xT + p * (INP * BSZ),
                                           g_h0T[rb], sW, aoff, boff);
            } else {
                // A = [h0(p-1) | h1(p-2)]
                gemm_tiles<NK8_1, HID / 8>(acc, g_h0T[rb],
                                           g_h1T[rb], sW, aoff, boff);
            }

            // LSTM cell update — all four gates for each (row, col) are in
            // this lane's registers (ntile index == gate group).
            float* cT = l0 ? g_c0T : g_c1T;
            float* hW = l0 ? g_h0T[wb] : g_h1T[wb];
#pragma unroll
            for (int pr = 0; pr < 4; ++pr) {
                int r = rowa + ((pr & 2) ? 8 : 0);
                int n = n0 + 2 * tig + (pr & 1);
                float gi = acc[0][pr], gf = acc[1][pr];
                float gg = acc[2][pr], go = acc[3][pr];
                float co = cT[n * BSZ + r];
                float cn = sigm(gf) * co + sigm(gi) * tanhf(gg);
                cT[n * BSZ + r] = cn;
                float h = sigm(go) * tanhf(cn);
                hW[n * BSZ + r] = __uint_as_float(f2tf32(h));  // pre-round for next GEMM
            }
        }
        grid_bar(gen);
    }

    // ---- epilogue: pred = h1(511) @ Wfc + bfc ; phase 512 wrote buffer 0 ----
    if (cta == 0 && tid < BSZ) {
        const float* h = g_h1T[0];
        float s0 = 0.f, s1 = 0.f, s2 = 0.f, s3 = 0.f;
#pragma unroll 4
        for (int n = 0; n < HID; n += 4) {
            s0 += __ldcg(h + (n + 0) * BSZ + tid) * Wfc[n + 0];
            s1 += __ldcg(h + (n + 1) * BSZ + tid) * Wfc[n + 1];
            s2 += __ldcg(h + (n + 2) * BSZ + tid) * Wfc[n + 2];
            s3 += __ldcg(h + (n + 3) * BSZ + tid) * Wfc[n + 3];
        }
        out[tid] = (s0 + s1) + (s2 + s3) + bfc[0];
    }

    // ---- exit: last CTA resets barrier counters for the next graph replay ----
    __syncthreads();
    if (tid == 0) {
        __threadfence();
        unsigned e = atomicAdd(&g_exit, 1u);
        if (e == NC - 1u) {
            atomicExch(&g_arrive, 0u);
            atomicExch(&g_release, 0u);
            atomicExch(&g_exit, 0u);
            __threadfence();
        }
    }
}

// x[b][t][i] -> xT[t][i][b], rounded to tf32 once.
__global__ void xpose_kernel(const float* __restrict__ x) {
    int idx = blockIdx.x * blockDim.x + threadIdx.x;
    if (idx < BSZ * SEQ * INP) {
        int i = idx & (INP - 1);
        int t = (idx >> 6) & (SEQ - 1);
        int b = idx >> 15;
        g_xT[(t * INP + i) * BSZ + b] = __uint_as_float(f2tf32(x[idx]));
    }
}

extern "C" void kernel_launch(void* const* d_in, const int* in_sizes, int n_in,
                              void* d_out, int out_size) {
    (void)in_sizes; (void)n_in; (void)out_size;
    const float* x   = (const float*)d_in[0];
    const float* W0  = (const float*)d_in[1];
    const float* b0  = (const float*)d_in[2];
    const float* W1  = (const float*)d_in[3];
    const float* b1  = (const float*)d_in[4];
    const float* Wfc = (const float*)d_in[5];
    const float* bfc = (const float*)d_in[6];
    float* out = (float*)d_out;

    cudaFuncSetAttribute(lstm_persist,
                         cudaFuncAttributeMaxDynamicSharedMemorySize, SMEM_BYTES);

    xpose_kernel<<<(BSZ * SEQ * INP + 255) / 256, 256>>>(x);
    lstm_persist<<<NC, NTHR, SMEM_BYTES>>>(W0, b0, W1, b1, Wfc, bfc, out);
}